// round 2
// baseline (speedup 1.0000x reference)
#include <cuda_runtime.h>
#include <cstdint>

#define N_MAX 50000
#define M_MAX 800000
#define D 128
#define DD 32

// Scratch (no allocs allowed) — __device__ globals, 16B-aligned.
__device__ __align__(16) static float g_bufA[N_MAX * D];   // x after input GEMM
__device__ __align__(16) static float g_xn[N_MAX * D];     // channel-normalized x (layer residual)
__device__ __align__(16) static float g_c[N_MAX * D];      // current routing state (normalized)
__device__ __align__(16) static float g_cnew[N_MAX * D];   // scatter target
__device__ __align__(16) static float g_s[N_MAX * DD];     // per-node group sums
__device__ static int g_src[M_MAX];
__device__ static int g_trg[M_MAX];
__device__ static int g_is64;                               // edge_index dtype flag

// ------------------------------------------------- dtype detect (int32 vs int64)
// If the buffer is int64 (values < 2^31), every odd 32-bit word is 0.
__global__ void detect_kernel(const int* __restrict__ p) {
    if (threadIdx.x == 0 && blockIdx.x == 0) {
        int any_nonzero = 0;
        for (int i = 0; i < 256; i++) any_nonzero |= p[2 * i + 1];
        g_is64 = (any_nonzero == 0) ? 1 : 0;
    }
}

// ---------------------------------------------------------------- idx convert
__global__ void idx_kernel(const void* __restrict__ ei,
                           int* __restrict__ src, int* __restrict__ trg, int m) {
    int i = blockIdx.x * blockDim.x + threadIdx.x;
    if (i >= m) return;
    if (g_is64) {
        const long long* p = (const long long*)ei;
        src[i] = (int)p[i];
        trg[i] = (int)p[m + i];
    } else {
        const int* p = (const int*)ei;
        src[i] = p[i];
        trg[i] = p[m + i];
    }
}

// ---------------------------------------------------------------- GEMM + bias
// C[n,128] = A[n,128] @ W[128,128] + b.  BM=32 rows/block, 128 threads (1 col each).
#define BM 32
__global__ void gemm_bias_kernel(const float* __restrict__ A,
                                 const float* __restrict__ W,
                                 const float* __restrict__ b,
                                 float* __restrict__ C, int n) {
    __shared__ float As[BM * D];
    int j = threadIdx.x;               // output column 0..127
    int row0 = blockIdx.x * BM;
    int nvalid = n - row0; if (nvalid > BM) nvalid = BM;

    const float4* A4 = (const float4*)(A + (size_t)row0 * D);
    float4* As4 = (float4*)As;
    for (int i = threadIdx.x; i < nvalid * (D / 4); i += blockDim.x) As4[i] = A4[i];
    __syncthreads();

    float acc[BM];
#pragma unroll
    for (int r = 0; r < BM; r++) acc[r] = 0.f;

    for (int k = 0; k < D; k++) {
        float w = W[k * D + j];
#pragma unroll
        for (int r = 0; r < BM; r++) acc[r] = fmaf(As[r * D + k], w, acc[r]);
    }
    float bj = b[j];
    for (int r = 0; r < nvalid; r++) C[(size_t)(row0 + r) * D + j] = acc[r] + bj;
}

// ------------------------------------------------------- channel normalize
// warp per node; 8-lane groups = one 32-float channel. Writes out0 (and out1 if non-null).
__global__ void norm_kernel(const float* __restrict__ in,
                            float* __restrict__ out0, float* __restrict__ out1, int n) {
    int gw = (blockIdx.x * blockDim.x + threadIdx.x) >> 5;
    if (gw >= n) return;
    int lane = threadIdx.x & 31;
    float4 v = *(const float4*)(in + (size_t)gw * D + lane * 4);
    float ss = v.x * v.x + v.y * v.y + v.z * v.z + v.w * v.w;
    ss += __shfl_xor_sync(0xffffffffu, ss, 1);
    ss += __shfl_xor_sync(0xffffffffu, ss, 2);
    ss += __shfl_xor_sync(0xffffffffu, ss, 4);
    float inv = 1.0f / fmaxf(sqrtf(ss), 1e-12f);
    float4 o = make_float4(v.x * inv, v.y * inv, v.z * inv, v.w * inv);
    *(float4*)(out0 + (size_t)gw * D + lane * 4) = o;
    if (out1) *(float4*)(out1 + (size_t)gw * D + lane * 4) = o;
}

// -------------------------------------------- per-node group sums of 4
// s[node][a] = sum of c[node][4a .. 4a+3]
__global__ void gsum_kernel(const float* __restrict__ c, float* __restrict__ s, int n) {
    int gw = (blockIdx.x * blockDim.x + threadIdx.x) >> 5;
    if (gw >= n) return;
    int lane = threadIdx.x & 31;
    float4 v = *(const float4*)(c + (size_t)gw * D + lane * 4);
    s[(size_t)gw * DD + lane] = v.x + v.y + v.z + v.w;
}

// ------------------------------------------------------------- edge routing
// warp per edge. lane l owns elems [4l,4l+4); channel k = l/8.
__global__ void edge_kernel(const int* __restrict__ src, const int* __restrict__ trg,
                            const float* __restrict__ xn, const float* __restrict__ s_node,
                            float* __restrict__ cnew, int m) {
    int e = (blockIdx.x * blockDim.x + threadIdx.x) >> 5;
    if (e >= m) return;
    int lane = threadIdx.x & 31;
    int si = src[e], ti = trg[e];

    float4 z  = *(const float4*)(xn + (size_t)si * D + lane * 4);
    float4 s4 = *(const float4*)(s_node + (size_t)ti * DD + (lane & 7) * 4);

    float part = z.x * s4.x + z.y * s4.y + z.z * s4.z + z.w * s4.w;
    part += __shfl_xor_sync(0xffffffffu, part, 1);
    part += __shfl_xor_sync(0xffffffffu, part, 2);
    part += __shfl_xor_sync(0xffffffffu, part, 4);
    // part == logit p_k for this lane's channel
    float p0 = __shfl_sync(0xffffffffu, part, 0);
    float p1 = __shfl_sync(0xffffffffu, part, 8);
    float p2 = __shfl_sync(0xffffffffu, part, 16);
    float p3 = __shfl_sync(0xffffffffu, part, 24);
    float mx = fmaxf(fmaxf(p0, p1), fmaxf(p2, p3));
    float denom = __expf(p0 - mx) + __expf(p1 - mx) + __expf(p2 - mx) + __expf(p3 - mx);
    float w = __expf(part - mx) / denom;

    float* dst = cnew + (size_t)ti * D + lane * 4;
    asm volatile("red.global.add.v4.f32 [%0], {%1,%2,%3,%4};"
                 :: "l"(dst), "f"(w * z.x), "f"(w * z.y), "f"(w * z.z), "f"(w * z.w)
                 : "memory");
}

// ---------------------------------------------------------------- launch
extern "C" void kernel_launch(void* const* d_in, const int* in_sizes, int n_in,
                              void* d_out, int out_size) {
    const float* feat  = (const float*)d_in[0];
    const void*  ei    = d_in[1];
    const float* lin_w = (const float*)d_in[2];
    const float* lin_b = (const float*)d_in[3];
    const float* mlp_w = (const float*)d_in[4];
    const float* mlp_b = (const float*)d_in[5];

    int n = in_sizes[0] / D;
    int m = in_sizes[1] / 2;

    float *bufA, *xn, *c, *cnew, *snode;
    int *src, *trg;
    cudaGetSymbolAddress((void**)&bufA,  g_bufA);
    cudaGetSymbolAddress((void**)&xn,    g_xn);
    cudaGetSymbolAddress((void**)&c,     g_c);
    cudaGetSymbolAddress((void**)&cnew,  g_cnew);
    cudaGetSymbolAddress((void**)&snode, g_s);
    cudaGetSymbolAddress((void**)&src,   g_src);
    cudaGetSymbolAddress((void**)&trg,   g_trg);

    detect_kernel<<<1, 32>>>((const int*)ei);
    idx_kernel<<<(m + 255) / 256, 256>>>(ei, src, trg, m);

    // x = feat @ lin_w + lin_b
    gemm_bias_kernel<<<(n + BM - 1) / BM, 128>>>(feat, lin_w, lin_b, bufA, n);

    int node_blocks = (n * 32 + 255) / 256;   // warp per node
    int edge_blocks = (m + 7) / 8;            // warp per edge, 8 warps/block
    size_t nbytes = (size_t)n * D * sizeof(float);

    const float* x_in = bufA;
    for (int layer = 0; layer < 2; layer++) {
        // xn = normalize(x); c = xn
        norm_kernel<<<node_blocks, 256>>>(x_in, xn, c, n);
        for (int t = 0; t < 3; t++) {
            gsum_kernel<<<node_blocks, 256>>>(c, snode, n);
            cudaMemcpyAsync(cnew, xn, nbytes, cudaMemcpyDeviceToDevice, 0);
            edge_kernel<<<edge_blocks, 256>>>(src, trg, xn, snode, cnew, m);
            if (t < 2) norm_kernel<<<node_blocks, 256>>>(cnew, c, nullptr, n);
        }
        x_in = cnew;   // unnormalized final c of this layer
    }

    // out = x @ mlp_w + mlp_b  ->  d_out[0 : n*D]
    gemm_bias_kernel<<<(n + BM - 1) / BM, 128>>>(cnew, mlp_w, mlp_b, (float*)d_out, n);

    // second tuple element: x  ->  d_out[n*D : 2*n*D]
    if (out_size >= 2 * n * D)
        cudaMemcpyAsync((float*)d_out + (size_t)n * D, cnew, nbytes,
                        cudaMemcpyDeviceToDevice, 0);
}

// round 4
// speedup vs baseline: 1.3181x; 1.3181x over previous
#include <cuda_runtime.h>
#include <cstdint>

#define N_MAX 50000
#define M_MAX 800000
#define D 128

// Scratch — __device__ globals only (no allocs allowed).
__device__ __align__(16) static float g_bufA[N_MAX * D];   // x after input GEMM
__device__ __align__(16) static float g_xn[N_MAX * D];     // normalized layer input (residual base / z source)
__device__ __align__(16) static float g_c[N_MAX * D];      // current normalized routing state
__device__ __align__(16) static float g_cnew[N_MAX * D];   // layer output (unnormalized)
__device__ static int g_src[M_MAX];
__device__ static int g_trg[M_MAX];
__device__ static int g_deg[N_MAX];      // histogram, then reused nowhere
__device__ static int g_cnt[N_MAX];      // scatter cursors
__device__ static int g_rowptr[N_MAX + 1];
__device__ static int g_adj[M_MAX];      // incoming-edge src ids, grouped by trg
__device__ static int g_is64;            // edge_index dtype flag

// ------------------------------------------------- dtype detect (int32 vs int64)
__global__ void detect_kernel(const int* __restrict__ p) {
    if (threadIdx.x == 0 && blockIdx.x == 0) {
        int any = 0;
        for (int i = 0; i < 256; i++) any |= p[2 * i + 1];
        g_is64 = (any == 0) ? 1 : 0;
    }
}

// ---------------------------------------------------------------- idx convert
__global__ void idx_kernel(const void* __restrict__ ei,
                           int* __restrict__ src, int* __restrict__ trg, int m) {
    int i = blockIdx.x * blockDim.x + threadIdx.x;
    if (i >= m) return;
    if (g_is64) {
        const long long* p = (const long long*)ei;
        src[i] = (int)p[i];
        trg[i] = (int)p[m + i];
    } else {
        const int* p = (const int*)ei;
        src[i] = p[i];
        trg[i] = p[m + i];
    }
}

// ---------------------------------------------------------------- CSR build
__global__ void hist_kernel(const int* __restrict__ trg, int* __restrict__ deg, int m) {
    int i = blockIdx.x * blockDim.x + threadIdx.x;
    if (i < m) atomicAdd(&deg[trg[i]], 1);
}

// single-block exclusive scan of deg[0..n) -> rowptr[0..n]
__global__ void scan_kernel(const int* __restrict__ deg, int* __restrict__ rowptr, int n) {
    __shared__ int part[1024];
    int t = threadIdx.x;
    int chunk = (n + 1023) / 1024;
    int start = t * chunk;
    int end = start + chunk; if (end > n) end = n;
    int sum = 0;
    for (int i = start; i < end; i++) sum += deg[i];
    part[t] = sum;
    __syncthreads();
    for (int off = 1; off < 1024; off <<= 1) {
        int v = (t >= off) ? part[t - off] : 0;
        __syncthreads();
        part[t] += v;
        __syncthreads();
    }
    int run = (t == 0) ? 0 : part[t - 1];
    for (int i = start; i < end; i++) { rowptr[i] = run; run += deg[i]; }
    if (end == n && start < n) rowptr[n] = run;
}

__global__ void scatter_kernel(const int* __restrict__ src, const int* __restrict__ trg,
                               const int* __restrict__ rowptr, int* __restrict__ cnt,
                               int* __restrict__ adj, int m) {
    int i = blockIdx.x * blockDim.x + threadIdx.x;
    if (i >= m) return;
    int tg = trg[i];
    int pos = rowptr[tg] + atomicAdd(&cnt[tg], 1);
    adj[pos] = src[i];
}

// ---------------------------------------------------------------- GEMM + bias
#define BM 32
__global__ void gemm_bias_kernel(const float* __restrict__ A,
                                 const float* __restrict__ W,
                                 const float* __restrict__ b,
                                 float* __restrict__ C, int n) {
    __shared__ float As[BM * D];
    int j = threadIdx.x;
    int row0 = blockIdx.x * BM;
    int nvalid = n - row0; if (nvalid > BM) nvalid = BM;

    const float4* A4 = (const float4*)(A + (size_t)row0 * D);
    float4* As4 = (float4*)As;
    for (int i = threadIdx.x; i < nvalid * (D / 4); i += blockDim.x) As4[i] = A4[i];
    __syncthreads();

    float acc[BM];
#pragma unroll
    for (int r = 0; r < BM; r++) acc[r] = 0.f;
    for (int k = 0; k < D; k++) {
        float w = W[k * D + j];
#pragma unroll
        for (int r = 0; r < BM; r++) acc[r] = fmaf(As[r * D + k], w, acc[r]);
    }
    float bj = b[j];
    for (int r = 0; r < nvalid; r++) C[(size_t)(row0 + r) * D + j] = acc[r] + bj;
}

// ------------------------------------------------------- channel normalize
__global__ void norm_kernel(const float* __restrict__ in, float* __restrict__ out, int n) {
    int gw = (blockIdx.x * blockDim.x + threadIdx.x) >> 5;
    if (gw >= n) return;
    int lane = threadIdx.x & 31;
    float4 v = *(const float4*)(in + (size_t)gw * D + lane * 4);
    float ss = v.x * v.x + v.y * v.y + v.z * v.z + v.w * v.w;
    ss += __shfl_xor_sync(0xffffffffu, ss, 1);
    ss += __shfl_xor_sync(0xffffffffu, ss, 2);
    ss += __shfl_xor_sync(0xffffffffu, ss, 4);
    float inv = 1.0f / fmaxf(sqrtf(ss), 1e-12f);
    *(float4*)(out + (size_t)gw * D + lane * 4) =
        make_float4(v.x * inv, v.y * inv, v.z * inv, v.w * inv);
}

// ------------------------------------------- fused routing iteration
// warp per target node v. lane l holds elems [4l,4l+4); channel k = l/8.
// s[a] = sum of c[v][4a..4a+3]  (lane a's float4 sum).
// For the dot, lane l needs s[4*(l%8) + j], j=0..3  -> 4 variable-lane shfls.
template <bool DO_NORM>
__global__ void iter_kernel(const int* __restrict__ rowptr, const int* __restrict__ adj,
                            const float* __restrict__ xn, const float* __restrict__ c,
                            float* __restrict__ out, int n) {
    int v = (blockIdx.x * blockDim.x + threadIdx.x) >> 5;
    if (v >= n) return;
    int lane = threadIdx.x & 31;

    float4 cv = *(const float4*)(c + (size_t)v * D + lane * 4);
    float sv = cv.x + cv.y + cv.z + cv.w;
    int b = (lane & 7) * 4;
    float s0 = __shfl_sync(0xffffffffu, sv, b);
    float s1 = __shfl_sync(0xffffffffu, sv, b + 1);
    float s2 = __shfl_sync(0xffffffffu, sv, b + 2);
    float s3 = __shfl_sync(0xffffffffu, sv, b + 3);

    float4 acc = *(const float4*)(xn + (size_t)v * D + lane * 4);  // residual

    int beg = rowptr[v], end = rowptr[v + 1];
    for (int i = beg; i < end; i++) {
        int s = adj[i];  // uniform across warp
        float4 z = *(const float4*)(xn + (size_t)s * D + lane * 4);
        float part = z.x * s0 + z.y * s1 + z.z * s2 + z.w * s3;
        part += __shfl_xor_sync(0xffffffffu, part, 1);
        part += __shfl_xor_sync(0xffffffffu, part, 2);
        part += __shfl_xor_sync(0xffffffffu, part, 4);
        float p0 = __shfl_sync(0xffffffffu, part, 0);
        float p1 = __shfl_sync(0xffffffffu, part, 8);
        float p2 = __shfl_sync(0xffffffffu, part, 16);
        float p3 = __shfl_sync(0xffffffffu, part, 24);
        float mx = fmaxf(fmaxf(p0, p1), fmaxf(p2, p3));
        float den = __expf(p0 - mx) + __expf(p1 - mx) + __expf(p2 - mx) + __expf(p3 - mx);
        float w = __expf(part - mx) / den;
        acc.x = fmaf(w, z.x, acc.x);
        acc.y = fmaf(w, z.y, acc.y);
        acc.z = fmaf(w, z.z, acc.z);
        acc.w = fmaf(w, z.w, acc.w);
    }

    if (DO_NORM) {
        float ss = acc.x * acc.x + acc.y * acc.y + acc.z * acc.z + acc.w * acc.w;
        ss += __shfl_xor_sync(0xffffffffu, ss, 1);
        ss += __shfl_xor_sync(0xffffffffu, ss, 2);
        ss += __shfl_xor_sync(0xffffffffu, ss, 4);
        float inv = 1.0f / fmaxf(sqrtf(ss), 1e-12f);
        acc.x *= inv; acc.y *= inv; acc.z *= inv; acc.w *= inv;
    }
    *(float4*)(out + (size_t)v * D + lane * 4) = acc;
}

// ---------------------------------------------------------------- launch
extern "C" void kernel_launch(void* const* d_in, const int* in_sizes, int n_in,
                              void* d_out, int out_size) {
    const float* feat  = (const float*)d_in[0];
    const void*  ei    = d_in[1];
    const float* lin_w = (const float*)d_in[2];
    const float* lin_b = (const float*)d_in[3];
    const float* mlp_w = (const float*)d_in[4];
    const float* mlp_b = (const float*)d_in[5];

    int n = in_sizes[0] / D;
    int m = in_sizes[1] / 2;

    float *bufA, *xn, *c, *cnew;
    int *src, *trg, *deg, *cnt, *rowptr, *adj;
    cudaGetSymbolAddress((void**)&bufA,   g_bufA);
    cudaGetSymbolAddress((void**)&xn,     g_xn);
    cudaGetSymbolAddress((void**)&c,      g_c);
    cudaGetSymbolAddress((void**)&cnew,   g_cnew);
    cudaGetSymbolAddress((void**)&src,    g_src);
    cudaGetSymbolAddress((void**)&trg,    g_trg);
    cudaGetSymbolAddress((void**)&deg,    g_deg);
    cudaGetSymbolAddress((void**)&cnt,    g_cnt);
    cudaGetSymbolAddress((void**)&rowptr, g_rowptr);
    cudaGetSymbolAddress((void**)&adj,    g_adj);

    // ---- edge preprocessing + CSR build (once per call)
    detect_kernel<<<1, 32>>>((const int*)ei);
    idx_kernel<<<(m + 255) / 256, 256>>>(ei, src, trg, m);
    cudaMemsetAsync(deg, 0, (size_t)n * sizeof(int), 0);
    cudaMemsetAsync(cnt, 0, (size_t)n * sizeof(int), 0);
    hist_kernel<<<(m + 255) / 256, 256>>>(trg, deg, m);
    scan_kernel<<<1, 1024>>>(deg, rowptr, n);
    scatter_kernel<<<(m + 255) / 256, 256>>>(src, trg, rowptr, cnt, adj, m);

    // ---- x = feat @ lin_w + lin_b
    gemm_bias_kernel<<<(n + BM - 1) / BM, 128>>>(feat, lin_w, lin_b, bufA, n);

    int node_blocks = (n * 32 + 255) / 256;  // warp per node
    size_t nbytes = (size_t)n * D * sizeof(float);

    const float* x_in = bufA;
    for (int layer = 0; layer < 2; layer++) {
        norm_kernel<<<node_blocks, 256>>>(x_in, xn, n);
        // t=0: c == xn
        iter_kernel<true ><<<node_blocks, 256>>>(rowptr, adj, xn, xn, c, n);
        // t=1
        iter_kernel<true ><<<node_blocks, 256>>>(rowptr, adj, xn, c, c, n);
        // t=2: raw output
        iter_kernel<false><<<node_blocks, 256>>>(rowptr, adj, xn, c, cnew, n);
        x_in = cnew;
    }

    // out = x @ mlp_w + mlp_b
    gemm_bias_kernel<<<(n + BM - 1) / BM, 128>>>(cnew, mlp_w, mlp_b, (float*)d_out, n);
    // second tuple element: x
    if (out_size >= 2 * n * D)
        cudaMemcpyAsync((float*)d_out + (size_t)n * D, cnew, nbytes,
                        cudaMemcpyDeviceToDevice, 0);
}